// round 1
// baseline (speedup 1.0000x reference)
#include <cuda_runtime.h>
#include <cuda_bf16.h>
#include <cstdint>

// Problem constants (fixed shapes from reference)
#define BATCH 4096
#define DIM   4096

static __device__ float g_sin[(size_t)BATCH * DIM];
static __device__ float g_cos[(size_t)BATCH * DIM];

// ---------------------------------------------------------------------------
// Pass 1: elementwise sincos(x) -> scratch (memory bound, ~30us)
// ---------------------------------------------------------------------------
__global__ void sincos_kernel(const float* __restrict__ x) {
    int i = blockIdx.x * blockDim.x + threadIdx.x;  // float4 index
    float4 v = reinterpret_cast<const float4*>(x)[i];
    float4 s, c;
    sincosf(v.x, &s.x, &c.x);
    sincosf(v.y, &s.y, &c.y);
    sincosf(v.z, &s.z, &c.z);
    sincosf(v.w, &s.w, &c.w);
    reinterpret_cast<float4*>(g_sin)[i] = s;
    reinterpret_cast<float4*>(g_cos)[i] = c;
}

// ---------------------------------------------------------------------------
// Pass 2: fused dual GEMM + epilogue.
//   kc[b,i] = sum_j kappa[i,j] * cos(x[b,j])
//   ks[b,i] = sum_j kappa[i,j] * sin(x[b,j])
//   out[b,i] = wrap(x[b,i] + DT*(omega[i] + sin(x_bi)*kc - cos(x_bi)*ks))
// Both A operands (sin / cos tiles) share one kappa tile in smem.
// ---------------------------------------------------------------------------
#define BM 128
#define BN 64
#define BK 16
#define TM 8
#define TN 4
#define BMP (BM + 4)   // 132 floats = 528B, 16B-aligned rows
#define BNP (BN + 4)   // 68 floats  = 272B, 16B-aligned rows

__global__ __launch_bounds__(256, 2)
void resonator_gemm_kernel(const float* __restrict__ x,
                           const float* __restrict__ kappa,
                           const float* __restrict__ omega,
                           float* __restrict__ out) {
    __shared__ float sS[BK][BMP];   // sin tile, transposed [k][m]
    __shared__ float sC[BK][BMP];   // cos tile, transposed [k][m]
    __shared__ float sB[BK][BNP];   // kappa tile, transposed [k][n]

    const int tid  = threadIdx.x;
    const int trow = tid >> 4;      // 0..15  (M direction)
    const int tcol = tid & 15;      // 0..15  (N direction)

    const int bm = blockIdx.y * BM;
    const int bn = blockIdx.x * BN;

    // Global-load assignment:
    //  A tiles: 128 rows x 4 k-groups of float4 = 512 loads -> 2 per thread
    //  B tile :  64 rows x 4 k-groups            = 256 loads -> 1 per thread
    const int a_r0 = tid >> 2;            // 0..63
    const int a_kg = (tid & 3) * 4;       // 0,4,8,12 (k offset within stage)

    const float* __restrict__ sinA0 = g_sin + (size_t)(bm + a_r0) * DIM + a_kg;
    const float* __restrict__ sinA1 = sinA0 + (size_t)64 * DIM;
    const float* __restrict__ cosA0 = g_cos + (size_t)(bm + a_r0) * DIM + a_kg;
    const float* __restrict__ cosA1 = cosA0 + (size_t)64 * DIM;
    const float* __restrict__ Bptr  = kappa + (size_t)(bn + a_r0) * DIM + a_kg;

    float acc_kc[TM][TN];
    float acc_ks[TM][TN];
#pragma unroll
    for (int m = 0; m < TM; ++m)
#pragma unroll
        for (int n = 0; n < TN; ++n) { acc_kc[m][n] = 0.f; acc_ks[m][n] = 0.f; }

    // prefetch registers
    float4 pS0, pS1, pC0, pC1, pB;

    // initial load (stage k0 = 0)
    pS0 = *reinterpret_cast<const float4*>(sinA0);
    pS1 = *reinterpret_cast<const float4*>(sinA1);
    pC0 = *reinterpret_cast<const float4*>(cosA0);
    pC1 = *reinterpret_cast<const float4*>(cosA1);
    pB  = *reinterpret_cast<const float4*>(Bptr);

    for (int k0 = 0; k0 < DIM; k0 += BK) {
        // store current stage to smem (scatter transpose)
        sS[a_kg + 0][a_r0] = pS0.x;  sS[a_kg + 1][a_r0] = pS0.y;
        sS[a_kg + 2][a_r0] = pS0.z;  sS[a_kg + 3][a_r0] = pS0.w;
        sS[a_kg + 0][a_r0 + 64] = pS1.x;  sS[a_kg + 1][a_r0 + 64] = pS1.y;
        sS[a_kg + 2][a_r0 + 64] = pS1.z;  sS[a_kg + 3][a_r0 + 64] = pS1.w;

        sC[a_kg + 0][a_r0] = pC0.x;  sC[a_kg + 1][a_r0] = pC0.y;
        sC[a_kg + 2][a_r0] = pC0.z;  sC[a_kg + 3][a_r0] = pC0.w;
        sC[a_kg + 0][a_r0 + 64] = pC1.x;  sC[a_kg + 1][a_r0 + 64] = pC1.y;
        sC[a_kg + 2][a_r0 + 64] = pC1.z;  sC[a_kg + 3][a_r0 + 64] = pC1.w;

        sB[a_kg + 0][a_r0] = pB.x;  sB[a_kg + 1][a_r0] = pB.y;
        sB[a_kg + 2][a_r0] = pB.z;  sB[a_kg + 3][a_r0] = pB.w;

        __syncthreads();

        // prefetch next stage while computing
        if (k0 + BK < DIM) {
            const int koff = k0 + BK;
            pS0 = *reinterpret_cast<const float4*>(sinA0 + koff);
            pS1 = *reinterpret_cast<const float4*>(sinA1 + koff);
            pC0 = *reinterpret_cast<const float4*>(cosA0 + koff);
            pC1 = *reinterpret_cast<const float4*>(cosA1 + koff);
            pB  = *reinterpret_cast<const float4*>(Bptr  + koff);
        }

#pragma unroll
        for (int kk = 0; kk < BK; ++kk) {
            float4 s0 = *reinterpret_cast<const float4*>(&sS[kk][trow * TM]);
            float4 s1 = *reinterpret_cast<const float4*>(&sS[kk][trow * TM + 4]);
            float4 c0 = *reinterpret_cast<const float4*>(&sC[kk][trow * TM]);
            float4 c1 = *reinterpret_cast<const float4*>(&sC[kk][trow * TM + 4]);
            float4 bv = *reinterpret_cast<const float4*>(&sB[kk][tcol * TN]);

            float as[TM] = {s0.x, s0.y, s0.z, s0.w, s1.x, s1.y, s1.z, s1.w};
            float ac[TM] = {c0.x, c0.y, c0.z, c0.w, c1.x, c1.y, c1.z, c1.w};
            float bb[TN] = {bv.x, bv.y, bv.z, bv.w};

#pragma unroll
            for (int m = 0; m < TM; ++m) {
#pragma unroll
                for (int n = 0; n < TN; ++n) {
                    acc_kc[m][n] = fmaf(ac[m], bb[n], acc_kc[m][n]);
                    acc_ks[m][n] = fmaf(as[m], bb[n], acc_ks[m][n]);
                }
            }
        }
        __syncthreads();
    }

    // -------------------- epilogue --------------------
    const float DT = 0.1f;
    const float PI_F  = 3.14159265358979323846f;
    const float TWO_PI_F = 6.28318530717958647692f;

#pragma unroll
    for (int m = 0; m < TM; ++m) {
        const int b = bm + trow * TM + m;
        const size_t rowoff = (size_t)b * DIM;
#pragma unroll
        for (int n = 0; n < TN; ++n) {
            const int i = bn + tcol * TN + n;
            const float si = g_sin[rowoff + i];
            const float ci = g_cos[rowoff + i];
            const float upd = si * acc_kc[m][n] - ci * acc_ks[m][n];
            float v = x[rowoff + i] + DT * (omega[i] + upd);
            // wrap to [-pi, pi): (v + pi) mod 2pi - pi  (python-style mod)
            float t = fmodf(v + PI_F, TWO_PI_F);
            if (t < 0.f) t += TWO_PI_F;
            if (t >= TWO_PI_F) t -= TWO_PI_F;
            out[rowoff + i] = t - PI_F;
        }
    }
}

// ---------------------------------------------------------------------------
extern "C" void kernel_launch(void* const* d_in, const int* in_sizes, int n_in,
                              void* d_out, int out_size) {
    const float* x     = (const float*)d_in[0];
    const float* kappa = (const float*)d_in[1];
    const float* omega = (const float*)d_in[2];
    float* out = (float*)d_out;

    // Pass 1: sincos
    {
        const int total4 = (BATCH * DIM) / 4;
        const int threads = 256;
        sincos_kernel<<<total4 / threads, threads>>>(x);
    }
    // Pass 2: fused dual GEMM + wrap epilogue
    {
        dim3 grid(DIM / BN, BATCH / BM);
        resonator_gemm_kernel<<<grid, 256>>>(x, kappa, omega, out);
    }
}

// round 4
// speedup vs baseline: 1.0893x; 1.0893x over previous
#include <cuda_runtime.h>
#include <cstdint>

#define BATCH 4096
#define DIM   4096
#define NTOT  ((size_t)BATCH * (size_t)DIM)

// ---------------------------------------------------------------------------
// Device scratch: exact-tf32 hi/lo splits of sin(x), cos(x), kappa
// ---------------------------------------------------------------------------
static __device__ __align__(128) float g_shi[NTOT];
static __device__ __align__(128) float g_slo[NTOT];
static __device__ __align__(128) float g_chi[NTOT];
static __device__ __align__(128) float g_clo[NTOT];
static __device__ __align__(128) float g_khi[NTOT];
static __device__ __align__(128) float g_klo[NTOT];

// cvt.rna.tf32.f32 writes a .b32 destination -> must use "r" constraint
__device__ __forceinline__ float tf32_rna(float v) {
    uint32_t r;
    asm("cvt.rna.tf32.f32 %0, %1;" : "=r"(r) : "f"(v));
    return __uint_as_float(r);
}
__device__ __forceinline__ uint32_t smem_u32(const void* p) {
    uint32_t a;
    asm("{ .reg .u64 t; cvta.to.shared.u64 t, %1; cvt.u32.u64 %0, t; }" : "=r"(a) : "l"(p));
    return a;
}
__device__ __forceinline__ void cp_async16(uint32_t saddr, const void* gaddr) {
    asm volatile("cp.async.cg.shared.global [%0], [%1], 16;" :: "r"(saddr), "l"(gaddr));
}
#define CP_COMMIT() asm volatile("cp.async.commit_group;" ::: "memory")
#define CP_WAIT1()  asm volatile("cp.async.wait_group 1;" ::: "memory")
#define CP_WAIT0()  asm volatile("cp.async.wait_group 0;" ::: "memory")

// m16n8k8 tf32 MMA (sm_80 ISA -> HMMA on sm_100, no 'a' feature needed)
__device__ __forceinline__ void mma_tf32(float* d, const uint32_t* a, const uint32_t* b) {
    asm volatile(
        "mma.sync.aligned.m16n8k8.row.col.f32.tf32.tf32.f32 "
        "{%0,%1,%2,%3},{%4,%5,%6,%7},{%8,%9},{%0,%1,%2,%3};"
        : "+f"(d[0]), "+f"(d[1]), "+f"(d[2]), "+f"(d[3])
        : "r"(a[0]), "r"(a[1]), "r"(a[2]), "r"(a[3]), "r"(b[0]), "r"(b[1]));
}

// ---------------------------------------------------------------------------
// Prepasses
// ---------------------------------------------------------------------------
__global__ void split_kappa_kernel(const float* __restrict__ kappa) {
    size_t i = (size_t)blockIdx.x * blockDim.x + threadIdx.x;
    float4 v = reinterpret_cast<const float4*>(kappa)[i];
    float4 h, l;
    h.x = tf32_rna(v.x); l.x = tf32_rna(v.x - h.x);
    h.y = tf32_rna(v.y); l.y = tf32_rna(v.y - h.y);
    h.z = tf32_rna(v.z); l.z = tf32_rna(v.z - h.z);
    h.w = tf32_rna(v.w); l.w = tf32_rna(v.w - h.w);
    reinterpret_cast<float4*>(g_khi)[i] = h;
    reinterpret_cast<float4*>(g_klo)[i] = l;
}

__global__ void split_x_kernel(const float* __restrict__ x) {
    size_t i = (size_t)blockIdx.x * blockDim.x + threadIdx.x;
    float4 v = reinterpret_cast<const float4*>(x)[i];
    float4 s, c, sh, sl, ch, cl;
    sincosf(v.x, &s.x, &c.x);
    sincosf(v.y, &s.y, &c.y);
    sincosf(v.z, &s.z, &c.z);
    sincosf(v.w, &s.w, &c.w);
    sh.x = tf32_rna(s.x); sl.x = tf32_rna(s.x - sh.x);
    ch.x = tf32_rna(c.x); cl.x = tf32_rna(c.x - ch.x);
    sh.y = tf32_rna(s.y); sl.y = tf32_rna(s.y - sh.y);
    ch.y = tf32_rna(c.y); cl.y = tf32_rna(c.y - ch.y);
    sh.z = tf32_rna(s.z); sl.z = tf32_rna(s.z - sh.z);
    ch.z = tf32_rna(c.z); cl.z = tf32_rna(c.z - ch.z);
    sh.w = tf32_rna(s.w); sl.w = tf32_rna(s.w - sh.w);
    ch.w = tf32_rna(c.w); cl.w = tf32_rna(c.w - ch.w);
    reinterpret_cast<float4*>(g_shi)[i] = sh;
    reinterpret_cast<float4*>(g_slo)[i] = sl;
    reinterpret_cast<float4*>(g_chi)[i] = ch;
    reinterpret_cast<float4*>(g_clo)[i] = cl;
}

// ---------------------------------------------------------------------------
// Main kernel: dual 3xTF32 GEMM via mma.sync + fused epilogue
//   CTA tile 128x128, 512 threads (16 warps, 4x4), warp tile 32x32.
// ---------------------------------------------------------------------------
#define BK 16
#define TPAD (BK + 4)                 // 20 floats per smem row
#define TILE_FLOATS (128 * TPAD)      // 2560
#define TILE_B (TILE_FLOATS * 4)      // 10240 bytes
#define STAGE_B (6 * TILE_B)          // 61440 bytes
#define NBUF 3
#define SM_TOTAL (NBUF * STAGE_B)     // 184320 bytes
#define NSTAGES (DIM / BK)            // 256

// tile order within a stage
#define T_CHI 0
#define T_CLO 1
#define T_SHI 2
#define T_SLO 3
#define T_KHI 4
#define T_KLO 5

__global__ __launch_bounds__(512, 1)
void resonator_mma_kernel(const float* __restrict__ x,
                          const float* __restrict__ omega,
                          float* __restrict__ out) {
    extern __shared__ __align__(128) float smem[];
    const uint32_t sbase = smem_u32(smem);

    const int tid  = threadIdx.x;
    const int wid  = tid >> 5;
    const int lane = tid & 31;
    const int g    = lane >> 2;   // group id 0..7
    const int tg   = lane & 3;    // thread-in-group 0..3

    // ---- supertile-swizzled tile coords (32x32 tile grid, 8-wide groups) ----
    const int bid = blockIdx.x;
    const int GROUP = 8;
    const int sg = bid / (32 * GROUP);
    const int r  = bid % (32 * GROUP);
    const int ty = r / GROUP;
    const int tx = sg * GROUP + (r % GROUP);
    const int bm = ty * 128;
    const int bn = tx * 128;

    // warp position: 4x4 grid, warp tile 32x32
    const int wm = (wid >> 2) * 32;
    const int wn = (wid & 3) * 32;

    // ---- global loader assignment: row = tid/4, float4 chunk = tid%4 ----
    const int lrow = tid >> 2;
    const int lch  = tid & 3;
    const size_t gA = (size_t)(bm + lrow) * DIM + lch * 4;
    const size_t gB = (size_t)(bn + lrow) * DIM + lch * 4;
    const float* pG[6];
    pG[T_CHI] = g_chi + gA;
    pG[T_CLO] = g_clo + gA;
    pG[T_SHI] = g_shi + gA;
    pG[T_SLO] = g_slo + gA;
    pG[T_KHI] = g_khi + gB;
    pG[T_KLO] = g_klo + gB;
    const uint32_t sW = sbase + (uint32_t)(lrow * TPAD + lch * 4) * 4;

    // accumulators
    float kc[2][4][4];
    float ks[2][4][4];
#pragma unroll
    for (int mt = 0; mt < 2; ++mt)
#pragma unroll
        for (int nt = 0; nt < 4; ++nt)
#pragma unroll
            for (int e = 0; e < 4; ++e) { kc[mt][nt][e] = 0.f; ks[mt][nt][e] = 0.f; }

    // prologue: stages 0,1
#pragma unroll
    for (int p = 0; p < 2; ++p) {
        const uint32_t sb = sW + p * STAGE_B;
#pragma unroll
        for (int t = 0; t < 6; ++t)
            cp_async16(sb + t * TILE_B, pG[t] + (size_t)p * BK);
        CP_COMMIT();
    }

    for (int s = 0; s < NSTAGES; ++s) {
        if (s + 2 < NSTAGES) {
            const uint32_t sb = sW + ((s + 2) % NBUF) * STAGE_B;
            const size_t ko = (size_t)(s + 2) * BK;
#pragma unroll
            for (int t = 0; t < 6; ++t)
                cp_async16(sb + t * TILE_B, pG[t] + ko);
            CP_COMMIT();
            CP_WAIT1();
        } else {
            CP_WAIT0();
        }
        __syncthreads();

        const float* st = smem + ((s % NBUF) * STAGE_B) / 4;
        const float* tCHI = st + T_CHI * TILE_FLOATS;
        const float* tCLO = st + T_CLO * TILE_FLOATS;
        const float* tSHI = st + T_SHI * TILE_FLOATS;
        const float* tSLO = st + T_SLO * TILE_FLOATS;
        const float* tKHI = st + T_KHI * TILE_FLOATS;
        const float* tKLO = st + T_KLO * TILE_FLOATS;

#pragma unroll
        for (int kb = 0; kb < BK; kb += 8) {
            // B fragments (khi, klo): nt in 0..3, rows wn+nt*8+g, cols kb+tg/+4
            uint32_t bhi[4][2], blo[4][2];
#pragma unroll
            for (int nt = 0; nt < 4; ++nt) {
                const int brow = wn + nt * 8 + g;
                const int o0 = brow * TPAD + kb + tg;
                bhi[nt][0] = __float_as_uint(tKHI[o0]);
                bhi[nt][1] = __float_as_uint(tKHI[o0 + 4]);
                blo[nt][0] = __float_as_uint(tKLO[o0]);
                blo[nt][1] = __float_as_uint(tKLO[o0 + 4]);
            }

            uint32_t af[2][4];
            // chi: kc += chi*khi + chi*klo
#pragma unroll
            for (int mt = 0; mt < 2; ++mt) {
                const int arow = wm + mt * 16 + g;
                const int o0 = arow * TPAD + kb + tg;
                af[mt][0] = __float_as_uint(tCHI[o0]);
                af[mt][1] = __float_as_uint(tCHI[o0 + 8 * TPAD]);
                af[mt][2] = __float_as_uint(tCHI[o0 + 4]);
                af[mt][3] = __float_as_uint(tCHI[o0 + 8 * TPAD + 4]);
            }
#pragma unroll
            for (int mt = 0; mt < 2; ++mt)
#pragma unroll
                for (int nt = 0; nt < 4; ++nt) {
                    mma_tf32(kc[mt][nt], af[mt], bhi[nt]);
                    mma_tf32(kc[mt][nt], af[mt], blo[nt]);
                }
            // clo: kc += clo*khi
#pragma unroll
            for (int mt = 0; mt < 2; ++mt) {
                const int arow = wm + mt * 16 + g;
                const int o0 = arow * TPAD + kb + tg;
                af[mt][0] = __float_as_uint(tCLO[o0]);
                af[mt][1] = __float_as_uint(tCLO[o0 + 8 * TPAD]);
                af[mt][2] = __float_as_uint(tCLO[o0 + 4]);
                af[mt][3] = __float_as_uint(tCLO[o0 + 8 * TPAD + 4]);
            }
#pragma unroll
            for (int mt = 0; mt < 2; ++mt)
#pragma unroll
                for (int nt = 0; nt < 4; ++nt)
                    mma_tf32(kc[mt][nt], af[mt], bhi[nt]);
            // shi: ks += shi*khi + shi*klo
#pragma unroll
            for (int mt = 0; mt < 2; ++mt) {
                const int arow = wm + mt * 16 + g;
                const int o0 = arow * TPAD + kb + tg;
                af[mt][0] = __float_as_uint(tSHI[o0]);
                af[mt][1] = __float_as_uint(tSHI[o0 + 8 * TPAD]);
                af[mt][2] = __float_as_uint(tSHI[o0 + 4]);
                af[mt][3] = __float_as_uint(tSHI[o0 + 8 * TPAD + 4]);
            }
#pragma unroll
            for (int mt = 0; mt < 2; ++mt)
#pragma unroll
                for (int nt = 0; nt < 4; ++nt) {
                    mma_tf32(ks[mt][nt], af[mt], bhi[nt]);
                    mma_tf32(ks[mt][nt], af[mt], blo[nt]);
                }
            // slo: ks += slo*khi
#pragma unroll
            for (int mt = 0; mt < 2; ++mt) {
                const int arow = wm + mt * 16 + g;
                const int o0 = arow * TPAD + kb + tg;
                af[mt][0] = __float_as_uint(tSLO[o0]);
                af[mt][1] = __float_as_uint(tSLO[o0 + 8 * TPAD]);
                af[mt][2] = __float_as_uint(tSLO[o0 + 4]);
                af[mt][3] = __float_as_uint(tSLO[o0 + 8 * TPAD + 4]);
            }
#pragma unroll
            for (int mt = 0; mt < 2; ++mt)
#pragma unroll
                for (int nt = 0; nt < 4; ++nt)
                    mma_tf32(ks[mt][nt], af[mt], bhi[nt]);
        }
        __syncthreads();
    }

    // -------------------- fused epilogue --------------------
    const float DT = 0.1f;
    const float PI_F = 3.14159265358979323846f;
    const float TWO_PI_F = 6.28318530717958647692f;

#pragma unroll
    for (int mt = 0; mt < 2; ++mt) {
#pragma unroll
        for (int half = 0; half < 2; ++half) {  // c0/c1 (row g) vs c2/c3 (row g+8)
            const int b = bm + wm + mt * 16 + g + half * 8;
            const size_t rowoff = (size_t)b * DIM;
#pragma unroll
            for (int nt = 0; nt < 4; ++nt) {
                const int i = bn + wn + nt * 8 + tg * 2;
                const float akc0 = kc[mt][nt][half * 2 + 0];
                const float akc1 = kc[mt][nt][half * 2 + 1];
                const float aks0 = ks[mt][nt][half * 2 + 0];
                const float aks1 = ks[mt][nt][half * 2 + 1];

                float2 xv = *reinterpret_cast<const float2*>(x + rowoff + i);
                float2 ov = __ldg(reinterpret_cast<const float2*>(omega + i));
                float2 o;
                {
                    float sv, cv;
                    sincosf(xv.x, &sv, &cv);
                    float v = xv.x + DT * (ov.x + sv * akc0 - cv * aks0);
                    float t = fmodf(v + PI_F, TWO_PI_F);
                    if (t < 0.f) t += TWO_PI_F;
                    if (t >= TWO_PI_F) t -= TWO_PI_F;
                    o.x = t - PI_F;
                }
                {
                    float sv, cv;
                    sincosf(xv.y, &sv, &cv);
                    float v = xv.y + DT * (ov.y + sv * akc1 - cv * aks1);
                    float t = fmodf(v + PI_F, TWO_PI_F);
                    if (t < 0.f) t += TWO_PI_F;
                    if (t >= TWO_PI_F) t -= TWO_PI_F;
                    o.y = t - PI_F;
                }
                *reinterpret_cast<float2*>(out + rowoff + i) = o;
            }
        }
    }
}

// ---------------------------------------------------------------------------
extern "C" void kernel_launch(void* const* d_in, const int* in_sizes, int n_in,
                              void* d_out, int out_size) {
    const float* x     = (const float*)d_in[0];
    const float* kappa = (const float*)d_in[1];
    const float* omega = (const float*)d_in[2];
    float* out = (float*)d_out;

    cudaFuncSetAttribute(resonator_mma_kernel,
                         cudaFuncAttributeMaxDynamicSharedMemorySize, SM_TOTAL);

    const int f4 = (int)(NTOT / 4);
    split_kappa_kernel<<<f4 / 256, 256>>>(kappa);
    split_x_kernel<<<f4 / 256, 256>>>(x);
    resonator_mma_kernel<<<1024, 512, SM_TOTAL>>>(x, omega, out);
}

// round 6
// speedup vs baseline: 1.9324x; 1.7740x over previous
#include <cuda_runtime.h>
#include <cstdint>

#define BATCH 4096
#define DIM   4096
#define NTOT  ((size_t)BATCH * (size_t)DIM)

// ---------------------------------------------------------------------------
// Device scratch: tf32-rounded sin(x), cos(x), kappa + fixup candidate list
// ---------------------------------------------------------------------------
static __device__ __align__(128) float g_st[NTOT];
static __device__ __align__(128) float g_ct[NTOT];
static __device__ __align__(128) float g_kt[NTOT];

#define CAND_CAP 262144
static __device__ unsigned int g_cand_cnt;
static __device__ unsigned int g_cand[CAND_CAP];

__device__ __forceinline__ float tf32_rna(float v) {
    uint32_t r;
    asm("cvt.rna.tf32.f32 %0, %1;" : "=r"(r) : "f"(v));
    return __uint_as_float(r);
}
__device__ __forceinline__ uint32_t smem_u32(const void* p) {
    uint32_t a;
    asm("{ .reg .u64 t; cvta.to.shared.u64 t, %1; cvt.u32.u64 %0, t; }" : "=r"(a) : "l"(p));
    return a;
}
__device__ __forceinline__ void cp_async16(uint32_t saddr, const void* gaddr) {
    asm volatile("cp.async.cg.shared.global [%0], [%1], 16;" :: "r"(saddr), "l"(gaddr));
}
#define CP_COMMIT() asm volatile("cp.async.commit_group;" ::: "memory")
#define CP_WAIT1()  asm volatile("cp.async.wait_group 1;" ::: "memory")
#define CP_WAIT0()  asm volatile("cp.async.wait_group 0;" ::: "memory")

__device__ __forceinline__ void mma_tf32(float* d, const uint32_t* a, const uint32_t* b) {
    asm volatile(
        "mma.sync.aligned.m16n8k8.row.col.f32.tf32.tf32.f32 "
        "{%0,%1,%2,%3},{%4,%5,%6,%7},{%8,%9},{%0,%1,%2,%3};"
        : "+f"(d[0]), "+f"(d[1]), "+f"(d[2]), "+f"(d[3])
        : "r"(a[0]), "r"(a[1]), "r"(a[2]), "r"(a[3]), "r"(b[0]), "r"(b[1]));
}

__device__ __forceinline__ float wrap_pi(float v) {
    const float PI_F = 3.14159265358979323846f;
    const float TWO_PI_F = 6.28318530717958647692f;
    float t = fmodf(v + PI_F, TWO_PI_F);
    if (t < 0.f) t += TWO_PI_F;
    if (t >= TWO_PI_F) t -= TWO_PI_F;
    return t - PI_F;
}

// ---------------------------------------------------------------------------
// Prepasses
// ---------------------------------------------------------------------------
__global__ void prep_kappa(const float* __restrict__ kappa) {
    size_t i = (size_t)blockIdx.x * blockDim.x + threadIdx.x;
    float4 v = reinterpret_cast<const float4*>(kappa)[i];
    float4 h;
    h.x = tf32_rna(v.x);
    h.y = tf32_rna(v.y);
    h.z = tf32_rna(v.z);
    h.w = tf32_rna(v.w);
    reinterpret_cast<float4*>(g_kt)[i] = h;
}

__global__ void prep_x(const float* __restrict__ x) {
    size_t i = (size_t)blockIdx.x * blockDim.x + threadIdx.x;
    float4 v = reinterpret_cast<const float4*>(x)[i];
    float4 s, c;
    sincosf(v.x, &s.x, &c.x);
    sincosf(v.y, &s.y, &c.y);
    sincosf(v.z, &s.z, &c.z);
    sincosf(v.w, &s.w, &c.w);
    s.x = tf32_rna(s.x); c.x = tf32_rna(c.x);
    s.y = tf32_rna(s.y); c.y = tf32_rna(c.y);
    s.z = tf32_rna(s.z); c.z = tf32_rna(c.z);
    s.w = tf32_rna(s.w); c.w = tf32_rna(c.w);
    reinterpret_cast<float4*>(g_st)[i] = s;
    reinterpret_cast<float4*>(g_ct)[i] = c;
}

// ---------------------------------------------------------------------------
// Main GEMM: plain tf32, dual accumulators (kc, ks) sharing kappa fragments.
//   CTA 128x128, 256 threads, 8 warps (4M x 2N), warp tile 32x64, BK=32.
// ---------------------------------------------------------------------------
#define BK 32
#define TPAD (BK + 4)                 // 36 floats per smem row
#define TILEF (128 * TPAD)            // 4608 floats per tile
#define STAGEF (3 * TILEF)            // c, s, k
#define NBUF 3
#define SM_TOTAL (NBUF * STAGEF * 4)  // 165888 bytes
#define NSTAGES (DIM / BK)            // 128

__global__ __launch_bounds__(256, 1)
void resonator_mma_kernel(const float* __restrict__ x,
                          const float* __restrict__ omega,
                          float* __restrict__ out) {
    extern __shared__ __align__(128) float smem[];
    const uint32_t sbase = smem_u32(smem);

    const int tid  = threadIdx.x;
    const int wid  = tid >> 5;
    const int lane = tid & 31;
    const int g    = lane >> 2;
    const int tg   = lane & 3;

    // supertile swizzle (32x32 tile grid, 8-wide groups)
    const int bid = blockIdx.x;
    const int GROUP = 8;
    const int sg = bid / (32 * GROUP);
    const int r  = bid % (32 * GROUP);
    const int ty = r / GROUP;
    const int tx = sg * GROUP + (r % GROUP);
    const int bm = ty * 128;
    const int bn = tx * 128;

    const int wm = (wid >> 1) * 32;   // 4 M-warps
    const int wn = (wid & 1) * 64;    // 2 N-warps

    // loaders: row = tid/2, 4 contiguous float4 chunks at col base (tid&1)*16
    const int lrow = tid >> 1;
    const int cb0  = (tid & 1) * 16;  // float col base
    const float* pC = g_ct + (size_t)(bm + lrow) * DIM + cb0;
    const float* pS = g_st + (size_t)(bm + lrow) * DIM + cb0;
    const float* pK = g_kt + (size_t)(bn + lrow) * DIM + cb0;
    const uint32_t sRow = sbase + (uint32_t)(lrow * TPAD + cb0) * 4;

    float kc[2][8][4];
    float ks[2][8][4];
#pragma unroll
    for (int mt = 0; mt < 2; ++mt)
#pragma unroll
        for (int nt = 0; nt < 8; ++nt)
#pragma unroll
            for (int e = 0; e < 4; ++e) { kc[mt][nt][e] = 0.f; ks[mt][nt][e] = 0.f; }

    // prologue: stages 0,1
#pragma unroll
    for (int p = 0; p < 2; ++p) {
        const uint32_t sb = sRow + p * STAGEF * 4;
        const size_t ko = (size_t)p * BK;
#pragma unroll
        for (int j = 0; j < 4; ++j) {
            cp_async16(sb + 0 * TILEF * 4 + j * 16, pC + ko + j * 4);
            cp_async16(sb + 1 * TILEF * 4 + j * 16, pS + ko + j * 4);
            cp_async16(sb + 2 * TILEF * 4 + j * 16, pK + ko + j * 4);
        }
        CP_COMMIT();
    }

    for (int s = 0; s < NSTAGES; ++s) {
        if (s + 2 < NSTAGES) {
            const uint32_t sb = sRow + ((s + 2) % NBUF) * STAGEF * 4;
            const size_t ko = (size_t)(s + 2) * BK;
#pragma unroll
            for (int j = 0; j < 4; ++j) {
                cp_async16(sb + 0 * TILEF * 4 + j * 16, pC + ko + j * 4);
                cp_async16(sb + 1 * TILEF * 4 + j * 16, pS + ko + j * 4);
                cp_async16(sb + 2 * TILEF * 4 + j * 16, pK + ko + j * 4);
            }
            CP_COMMIT();
            CP_WAIT1();
        } else {
            CP_WAIT0();
        }
        __syncthreads();

        const float* st = smem + (s % NBUF) * STAGEF;
        const float* tC = st;
        const float* tS = st + TILEF;
        const float* tK = st + 2 * TILEF;

#pragma unroll
        for (int kb = 0; kb < BK; kb += 8) {
            uint32_t bh[8][2];
#pragma unroll
            for (int nt = 0; nt < 8; ++nt) {
                const int o0 = (wn + nt * 8 + g) * TPAD + kb + tg;
                bh[nt][0] = __float_as_uint(tK[o0]);
                bh[nt][1] = __float_as_uint(tK[o0 + 4]);
            }
            uint32_t ac[2][4], as_[2][4];
#pragma unroll
            for (int mt = 0; mt < 2; ++mt) {
                const int o0 = (wm + mt * 16 + g) * TPAD + kb + tg;
                ac[mt][0] = __float_as_uint(tC[o0]);
                ac[mt][1] = __float_as_uint(tC[o0 + 8 * TPAD]);
                ac[mt][2] = __float_as_uint(tC[o0 + 4]);
                ac[mt][3] = __float_as_uint(tC[o0 + 8 * TPAD + 4]);
                as_[mt][0] = __float_as_uint(tS[o0]);
                as_[mt][1] = __float_as_uint(tS[o0 + 8 * TPAD]);
                as_[mt][2] = __float_as_uint(tS[o0 + 4]);
                as_[mt][3] = __float_as_uint(tS[o0 + 8 * TPAD + 4]);
            }
#pragma unroll
            for (int mt = 0; mt < 2; ++mt)
#pragma unroll
                for (int nt = 0; nt < 8; ++nt) {
                    mma_tf32(kc[mt][nt], ac[mt], bh[nt]);
                    mma_tf32(ks[mt][nt], as_[mt], bh[nt]);
                }
        }
        __syncthreads();
    }

    // -------------------- fused epilogue --------------------
    const float DT = 0.1f;
#pragma unroll
    for (int mt = 0; mt < 2; ++mt) {
#pragma unroll
        for (int half = 0; half < 2; ++half) {
            const int b = bm + wm + mt * 16 + g + half * 8;
            const size_t rowoff = (size_t)b * DIM;
#pragma unroll
            for (int nt = 0; nt < 8; ++nt) {
                const int i = bn + wn + nt * 8 + tg * 2;
                float2 xv = *reinterpret_cast<const float2*>(x + rowoff + i);
                float2 ov = __ldg(reinterpret_cast<const float2*>(omega + i));
                float2 o;
                {
                    float sv, cv;
                    sincosf(xv.x, &sv, &cv);
                    float v = xv.x + DT * (ov.x + sv * kc[mt][nt][half * 2 + 0]
                                               - cv * ks[mt][nt][half * 2 + 0]);
                    o.x = wrap_pi(v);
                }
                {
                    float sv, cv;
                    sincosf(xv.y, &sv, &cv);
                    float v = xv.y + DT * (ov.y + sv * kc[mt][nt][half * 2 + 1]
                                               - cv * ks[mt][nt][half * 2 + 1]);
                    o.y = wrap_pi(v);
                }
                *reinterpret_cast<float2*>(out + rowoff + i) = o;
            }
        }
    }
}

// ---------------------------------------------------------------------------
// Fixup: find outputs near the wrap boundary, recompute them exactly in fp32.
// ---------------------------------------------------------------------------
__global__ void reset_cand() { g_cand_cnt = 0; }

__global__ void scan_boundary(const float* __restrict__ out) {
    const float PI_F = 3.14159265358979323846f;
    const float THR = 4e-3f;
    size_t i = (size_t)blockIdx.x * blockDim.x + threadIdx.x;  // float4 index
    float4 v = reinterpret_cast<const float4*>(out)[i];
    const float a0 = fabsf(fabsf(v.x) - PI_F);
    const float a1 = fabsf(fabsf(v.y) - PI_F);
    const float a2 = fabsf(fabsf(v.z) - PI_F);
    const float a3 = fabsf(fabsf(v.w) - PI_F);
    if (a0 < THR || a1 < THR || a2 < THR || a3 < THR) {
        unsigned base = (unsigned)(i * 4);
        if (a0 < THR) { unsigned k = atomicAdd(&g_cand_cnt, 1u); if (k < CAND_CAP) g_cand[k] = base + 0; }
        if (a1 < THR) { unsigned k = atomicAdd(&g_cand_cnt, 1u); if (k < CAND_CAP) g_cand[k] = base + 1; }
        if (a2 < THR) { unsigned k = atomicAdd(&g_cand_cnt, 1u); if (k < CAND_CAP) g_cand[k] = base + 2; }
        if (a3 < THR) { unsigned k = atomicAdd(&g_cand_cnt, 1u); if (k < CAND_CAP) g_cand[k] = base + 3; }
    }
}

__global__ void fixup_apply(const float* __restrict__ x,
                            const float* __restrict__ kappa,
                            const float* __restrict__ omega,
                            float* __restrict__ out) {
    const int warps_total = (gridDim.x * blockDim.x) >> 5;
    const int warp_id = ((blockIdx.x * blockDim.x) + threadIdx.x) >> 5;
    const int lane = threadIdx.x & 31;
    unsigned cnt = g_cand_cnt;
    if (cnt > CAND_CAP) cnt = CAND_CAP;

    for (unsigned w = warp_id; w < cnt; w += warps_total) {
        const unsigned idx = g_cand[w];
        const int b = (int)(idx / DIM);
        const int i = (int)(idx % DIM);
        const float* xrow = x + (size_t)b * DIM;
        const float* krow = kappa + (size_t)i * DIM;
        float kcv = 0.f, ksv = 0.f;
        for (int j = lane; j < DIM; j += 32) {
            float sv, cv;
            sincosf(xrow[j], &sv, &cv);
            const float kv = krow[j];
            kcv = fmaf(kv, cv, kcv);
            ksv = fmaf(kv, sv, ksv);
        }
#pragma unroll
        for (int off = 16; off > 0; off >>= 1) {
            kcv += __shfl_down_sync(0xFFFFFFFFu, kcv, off);
            ksv += __shfl_down_sync(0xFFFFFFFFu, ksv, off);
        }
        if (lane == 0) {
            const float xi = xrow[i];
            float sv, cv;
            sincosf(xi, &sv, &cv);
            const float v = xi + 0.1f * (omega[i] + sv * kcv - cv * ksv);
            out[idx] = wrap_pi(v);
        }
    }
}

// ---------------------------------------------------------------------------
extern "C" void kernel_launch(void* const* d_in, const int* in_sizes, int n_in,
                              void* d_out, int out_size) {
    const float* x     = (const float*)d_in[0];
    const float* kappa = (const float*)d_in[1];
    const float* omega = (const float*)d_in[2];
    float* out = (float*)d_out;

    cudaFuncSetAttribute(resonator_mma_kernel,
                         cudaFuncAttributeMaxDynamicSharedMemorySize, SM_TOTAL);

    const int f4 = (int)(NTOT / 4);
    prep_kappa<<<f4 / 256, 256>>>(kappa);
    prep_x<<<f4 / 256, 256>>>(x);
    resonator_mma_kernel<<<1024, 256, SM_TOTAL>>>(x, omega, out);
    reset_cand<<<1, 1>>>();
    scan_boundary<<<f4 / 256, 256>>>(out);
    fixup_apply<<<128, 256>>>(x, kappa, omega, out);
}

// round 7
// speedup vs baseline: 1.9621x; 1.0153x over previous
#include <cuda_runtime.h>
#include <cstdint>

#define BATCH 4096
#define DIM   4096
#define NTOT  ((size_t)BATCH * (size_t)DIM)

// ---------------------------------------------------------------------------
// Device scratch: tf32-rounded sin(x), cos(x), kappa + fixup candidate list
// ---------------------------------------------------------------------------
static __device__ __align__(128) float g_st[NTOT];
static __device__ __align__(128) float g_ct[NTOT];
static __device__ __align__(128) float g_kt[NTOT];

#define CAND_CAP 262144
static __device__ unsigned int g_cand_cnt;
static __device__ unsigned int g_cand[CAND_CAP];

__device__ __forceinline__ float tf32_rna(float v) {
    uint32_t r;
    asm("cvt.rna.tf32.f32 %0, %1;" : "=r"(r) : "f"(v));
    return __uint_as_float(r);
}
__device__ __forceinline__ uint32_t smem_u32(const void* p) {
    uint32_t a;
    asm("{ .reg .u64 t; cvta.to.shared.u64 t, %1; cvt.u32.u64 %0, t; }" : "=r"(a) : "l"(p));
    return a;
}
__device__ __forceinline__ void cp_async16(uint32_t saddr, const void* gaddr) {
    asm volatile("cp.async.cg.shared.global [%0], [%1], 16;" :: "r"(saddr), "l"(gaddr));
}
#define CP_COMMIT() asm volatile("cp.async.commit_group;" ::: "memory")
#define CP_WAIT1()  asm volatile("cp.async.wait_group 1;" ::: "memory")
#define CP_WAIT0()  asm volatile("cp.async.wait_group 0;" ::: "memory")

__device__ __forceinline__ void mma_tf32(float* d, const uint32_t* a, const uint32_t* b) {
    asm volatile(
        "mma.sync.aligned.m16n8k8.row.col.f32.tf32.tf32.f32 "
        "{%0,%1,%2,%3},{%4,%5,%6,%7},{%8,%9},{%0,%1,%2,%3};"
        : "+f"(d[0]), "+f"(d[1]), "+f"(d[2]), "+f"(d[3])
        : "r"(a[0]), "r"(a[1]), "r"(a[2]), "r"(a[3]), "r"(b[0]), "r"(b[1]));
}

// ldmatrix x4 over f32 data: each 8x8-b16 matrix = 8 rows x 4 f32 cols.
__device__ __forceinline__ void ldsm_x4(uint32_t* r, uint32_t addr) {
    asm volatile("ldmatrix.sync.aligned.m8n8.x4.shared.b16 {%0,%1,%2,%3}, [%4];"
        : "=r"(r[0]), "=r"(r[1]), "=r"(r[2]), "=r"(r[3]) : "r"(addr));
}

__device__ __forceinline__ float wrap_pi(float v) {
    const float PI_F = 3.14159265358979323846f;
    const float TWO_PI_F = 6.28318530717958647692f;
    float t = fmodf(v + PI_F, TWO_PI_F);
    if (t < 0.f) t += TWO_PI_F;
    if (t >= TWO_PI_F) t -= TWO_PI_F;
    return t - PI_F;
}

// ---------------------------------------------------------------------------
// Prepasses (reset_cand folded into prep_kappa)
// ---------------------------------------------------------------------------
__global__ void prep_kappa(const float* __restrict__ kappa) {
    if (blockIdx.x == 0 && threadIdx.x == 0) g_cand_cnt = 0;
    size_t i = (size_t)blockIdx.x * blockDim.x + threadIdx.x;
    float4 v = reinterpret_cast<const float4*>(kappa)[i];
    float4 h;
    h.x = tf32_rna(v.x);
    h.y = tf32_rna(v.y);
    h.z = tf32_rna(v.z);
    h.w = tf32_rna(v.w);
    reinterpret_cast<float4*>(g_kt)[i] = h;
}

__global__ void prep_x(const float* __restrict__ x) {
    size_t i = (size_t)blockIdx.x * blockDim.x + threadIdx.x;
    float4 v = reinterpret_cast<const float4*>(x)[i];
    float4 s, c;
    sincosf(v.x, &s.x, &c.x);
    sincosf(v.y, &s.y, &c.y);
    sincosf(v.z, &s.z, &c.z);
    sincosf(v.w, &s.w, &c.w);
    s.x = tf32_rna(s.x); c.x = tf32_rna(c.x);
    s.y = tf32_rna(s.y); c.y = tf32_rna(c.y);
    s.z = tf32_rna(s.z); c.z = tf32_rna(c.z);
    s.w = tf32_rna(s.w); c.w = tf32_rna(c.w);
    reinterpret_cast<float4*>(g_st)[i] = s;
    reinterpret_cast<float4*>(g_ct)[i] = c;
}

// ---------------------------------------------------------------------------
// Main GEMM: plain tf32, dual accumulators (kc, ks) sharing kappa fragments.
//   CTA 128x128, 256 threads, 8 warps (4M x 2N), warp tile 32x64, BK=32.
//   Fragment loads via ldmatrix.x4 (8 LDSM : 32 MMA per k8 step).
// ---------------------------------------------------------------------------
#define BK 32
#define TPAD (BK + 4)                 // 36 floats per smem row
#define TILEF (128 * TPAD)            // 4608 floats per tile
#define STAGEF (3 * TILEF)            // c, s, k
#define NBUF 3
#define SM_TOTAL (NBUF * STAGEF * 4)  // 165888 bytes
#define NSTAGES (DIM / BK)            // 128

__global__ __launch_bounds__(256, 1)
void resonator_mma_kernel(const float* __restrict__ x,
                          const float* __restrict__ omega,
                          float* __restrict__ out) {
    extern __shared__ __align__(128) float smem[];
    const uint32_t sbase = smem_u32(smem);

    const int tid  = threadIdx.x;
    const int wid  = tid >> 5;
    const int lane = tid & 31;
    const int g    = lane >> 2;
    const int tg   = lane & 3;

    // supertile swizzle (32x32 tile grid, 8-wide groups)
    const int bid = blockIdx.x;
    const int GROUP = 8;
    const int sg = bid / (32 * GROUP);
    const int r  = bid % (32 * GROUP);
    const int ty = r / GROUP;
    const int tx = sg * GROUP + (r % GROUP);
    const int bm = ty * 128;
    const int bn = tx * 128;

    const int wm = (wid >> 1) * 32;   // 4 M-warps
    const int wn = (wid & 1) * 64;    // 2 N-warps

    // loaders: row = tid/2, 4 contiguous float4 chunks at col base (tid&1)*16
    const int lrow = tid >> 1;
    const int cb0  = (tid & 1) * 16;  // float col base
    const float* pC = g_ct + (size_t)(bm + lrow) * DIM + cb0;
    const float* pS = g_st + (size_t)(bm + lrow) * DIM + cb0;
    const float* pK = g_kt + (size_t)(bn + lrow) * DIM + cb0;
    const uint32_t sRow = sbase + (uint32_t)(lrow * TPAD + cb0) * 4;

    // ldmatrix per-thread offsets (in floats, within a tile)
    // A (m16k8 fragment): matrices = (rows 0-7,k0),(rows 8-15,k0),(rows 0-7,k4),(rows 8-15,k4)
    int aoff[2];
#pragma unroll
    for (int mt = 0; mt < 2; ++mt)
        aoff[mt] = (wm + mt * 16 + (lane & 15)) * TPAD + ((lane >> 4) << 2);
    // B (two n8k8 fragments per x4): matrices = (n0-7,k0),(n0-7,k4),(n8-15,k0),(n8-15,k4)
    int boff[4];
#pragma unroll
    for (int ntp = 0; ntp < 4; ++ntp)
        boff[ntp] = (wn + ntp * 16 + (((lane >> 4) & 1) << 3) + (lane & 7)) * TPAD
                    + (((lane >> 3) & 1) << 2);

    float kc[2][8][4];
    float ks[2][8][4];
#pragma unroll
    for (int mt = 0; mt < 2; ++mt)
#pragma unroll
        for (int nt = 0; nt < 8; ++nt)
#pragma unroll
            for (int e = 0; e < 4; ++e) { kc[mt][nt][e] = 0.f; ks[mt][nt][e] = 0.f; }

    // prologue: stages 0,1
#pragma unroll
    for (int p = 0; p < 2; ++p) {
        const uint32_t sb = sRow + p * STAGEF * 4;
        const size_t ko = (size_t)p * BK;
#pragma unroll
        for (int j = 0; j < 4; ++j) {
            cp_async16(sb + 0 * TILEF * 4 + j * 16, pC + ko + j * 4);
            cp_async16(sb + 1 * TILEF * 4 + j * 16, pS + ko + j * 4);
            cp_async16(sb + 2 * TILEF * 4 + j * 16, pK + ko + j * 4);
        }
        CP_COMMIT();
    }

    for (int s = 0; s < NSTAGES; ++s) {
        if (s + 2 < NSTAGES) {
            const uint32_t sb = sRow + ((s + 2) % NBUF) * STAGEF * 4;
            const size_t ko = (size_t)(s + 2) * BK;
#pragma unroll
            for (int j = 0; j < 4; ++j) {
                cp_async16(sb + 0 * TILEF * 4 + j * 16, pC + ko + j * 4);
                cp_async16(sb + 1 * TILEF * 4 + j * 16, pS + ko + j * 4);
                cp_async16(sb + 2 * TILEF * 4 + j * 16, pK + ko + j * 4);
            }
            CP_COMMIT();
            CP_WAIT1();
        } else {
            CP_WAIT0();
        }
        __syncthreads();

        const uint32_t sb32 = sbase + (uint32_t)((s % NBUF) * STAGEF * 4);

#pragma unroll
        for (int kb = 0; kb < BK; kb += 8) {
            uint32_t bk[4][4];
#pragma unroll
            for (int ntp = 0; ntp < 4; ++ntp)
                ldsm_x4(bk[ntp], sb32 + 2 * TILEF * 4 + (uint32_t)(boff[ntp] + kb) * 4);
            uint32_t ac[2][4], as2[2][4];
#pragma unroll
            for (int mt = 0; mt < 2; ++mt) {
                ldsm_x4(ac[mt],  sb32 + 0 * TILEF * 4 + (uint32_t)(aoff[mt] + kb) * 4);
                ldsm_x4(as2[mt], sb32 + 1 * TILEF * 4 + (uint32_t)(aoff[mt] + kb) * 4);
            }
#pragma unroll
            for (int mt = 0; mt < 2; ++mt)
#pragma unroll
                for (int ntp = 0; ntp < 4; ++ntp) {
                    mma_tf32(kc[mt][2 * ntp],     ac[mt],  &bk[ntp][0]);
                    mma_tf32(kc[mt][2 * ntp + 1], ac[mt],  &bk[ntp][2]);
                    mma_tf32(ks[mt][2 * ntp],     as2[mt], &bk[ntp][0]);
                    mma_tf32(ks[mt][2 * ntp + 1], as2[mt], &bk[ntp][2]);
                }
        }
        __syncthreads();
    }

    // -------------------- fused epilogue --------------------
    const float DT = 0.1f;
#pragma unroll
    for (int mt = 0; mt < 2; ++mt) {
#pragma unroll
        for (int half = 0; half < 2; ++half) {
            const int b = bm + wm + mt * 16 + g + half * 8;
            const size_t rowoff = (size_t)b * DIM;
#pragma unroll
            for (int nt = 0; nt < 8; ++nt) {
                const int i = bn + wn + nt * 8 + tg * 2;
                float2 xv = *reinterpret_cast<const float2*>(x + rowoff + i);
                float2 ov = __ldg(reinterpret_cast<const float2*>(omega + i));
                float2 o;
                {
                    float sv, cv;
                    sincosf(xv.x, &sv, &cv);
                    float v = xv.x + DT * (ov.x + sv * kc[mt][nt][half * 2 + 0]
                                               - cv * ks[mt][nt][half * 2 + 0]);
                    o.x = wrap_pi(v);
                }
                {
                    float sv, cv;
                    sincosf(xv.y, &sv, &cv);
                    float v = xv.y + DT * (ov.y + sv * kc[mt][nt][half * 2 + 1]
                                               - cv * ks[mt][nt][half * 2 + 1]);
                    o.y = wrap_pi(v);
                }
                *reinterpret_cast<float2*>(out + rowoff + i) = o;
            }
        }
    }
}

// ---------------------------------------------------------------------------
// Fixup: find outputs near the wrap boundary, recompute them exactly in fp32.
// ---------------------------------------------------------------------------
__global__ void scan_boundary(const float* __restrict__ out) {
    const float PI_F = 3.14159265358979323846f;
    const float THR = 4e-3f;
    size_t i = (size_t)blockIdx.x * blockDim.x + threadIdx.x;  // float4 index
    float4 v = reinterpret_cast<const float4*>(out)[i];
    const float a0 = fabsf(fabsf(v.x) - PI_F);
    const float a1 = fabsf(fabsf(v.y) - PI_F);
    const float a2 = fabsf(fabsf(v.z) - PI_F);
    const float a3 = fabsf(fabsf(v.w) - PI_F);
    if (a0 < THR || a1 < THR || a2 < THR || a3 < THR) {
        unsigned base = (unsigned)(i * 4);
        if (a0 < THR) { unsigned k = atomicAdd(&g_cand_cnt, 1u); if (k < CAND_CAP) g_cand[k] = base + 0; }
        if (a1 < THR) { unsigned k = atomicAdd(&g_cand_cnt, 1u); if (k < CAND_CAP) g_cand[k] = base + 1; }
        if (a2 < THR) { unsigned k = atomicAdd(&g_cand_cnt, 1u); if (k < CAND_CAP) g_cand[k] = base + 2; }
        if (a3 < THR) { unsigned k = atomicAdd(&g_cand_cnt, 1u); if (k < CAND_CAP) g_cand[k] = base + 3; }
    }
}

__global__ void fixup_apply(const float* __restrict__ x,
                            const float* __restrict__ kappa,
                            const float* __restrict__ omega,
                            float* __restrict__ out) {
    const int warps_total = (gridDim.x * blockDim.x) >> 5;
    const int warp_id = ((blockIdx.x * blockDim.x) + threadIdx.x) >> 5;
    const int lane = threadIdx.x & 31;
    unsigned cnt = g_cand_cnt;
    if (cnt > CAND_CAP) cnt = CAND_CAP;

    for (unsigned w = warp_id; w < cnt; w += warps_total) {
        const unsigned idx = g_cand[w];
        const int b = (int)(idx / DIM);
        const int i = (int)(idx % DIM);
        const float* xrow = x + (size_t)b * DIM;
        const float* krow = kappa + (size_t)i * DIM;
        float kcv = 0.f, ksv = 0.f;
        for (int j = lane; j < DIM; j += 32) {
            float sv, cv;
            sincosf(xrow[j], &sv, &cv);
            const float kv = krow[j];
            kcv = fmaf(kv, cv, kcv);
            ksv = fmaf(kv, sv, ksv);
        }
#pragma unroll
        for (int off = 16; off > 0; off >>= 1) {
            kcv += __shfl_down_sync(0xFFFFFFFFu, kcv, off);
            ksv += __shfl_down_sync(0xFFFFFFFFu, ksv, off);
        }
        if (lane == 0) {
            const float xi = xrow[i];
            float sv, cv;
            sincosf(xi, &sv, &cv);
            const float v = xi + 0.1f * (omega[i] + sv * kcv - cv * ksv);
            out[idx] = wrap_pi(v);
        }
    }
}

// ---------------------------------------------------------------------------
extern "C" void kernel_launch(void* const* d_in, const int* in_sizes, int n_in,
                              void* d_out, int out_size) {
    const float* x     = (const float*)d_in[0];
    const float* kappa = (const float*)d_in[1];
    const float* omega = (const float*)d_in[2];
    float* out = (float*)d_out;

    cudaFuncSetAttribute(resonator_mma_kernel,
                         cudaFuncAttributeMaxDynamicSharedMemorySize, SM_TOTAL);

    const int f4 = (int)(NTOT / 4);
    prep_kappa<<<f4 / 256, 256>>>(kappa);
    prep_x<<<f4 / 256, 256>>>(x);
    resonator_mma_kernel<<<1024, 256, SM_TOTAL>>>(x, omega, out);
    scan_boundary<<<f4 / 256, 256>>>(out);
    fixup_apply<<<128, 256>>>(x, kappa, omega, out);
}

// round 8
// speedup vs baseline: 2.4276x; 1.2373x over previous
#include <cuda_runtime.h>
#include <cstdint>

#define BATCH 4096
#define DIM   4096
#define NTOT  ((size_t)BATCH * (size_t)DIM)

// ---------------------------------------------------------------------------
// Device scratch: int8 2-digit splits. v ~= h*2^-6 + l*2^-13 (|h|,|l| <= 64)
// kappa additionally scaled by g_kmax (global max |kappa|).
// ---------------------------------------------------------------------------
static __device__ __align__(128) signed char g_ch[NTOT];
static __device__ __align__(128) signed char g_cl[NTOT];
static __device__ __align__(128) signed char g_sh[NTOT];
static __device__ __align__(128) signed char g_sl[NTOT];
static __device__ __align__(128) signed char g_kh[NTOT];
static __device__ __align__(128) signed char g_kl[NTOT];
static __device__ unsigned int g_kmax_bits;

#define CAND_CAP 262144
static __device__ unsigned int g_cand_cnt;
static __device__ unsigned int g_cand[CAND_CAP];

__device__ __forceinline__ uint32_t smem_u32(const void* p) {
    uint32_t a;
    asm("{ .reg .u64 t; cvta.to.shared.u64 t, %1; cvt.u32.u64 %0, t; }" : "=r"(a) : "l"(p));
    return a;
}
__device__ __forceinline__ void cp_async16(uint32_t saddr, const void* gaddr) {
    asm volatile("cp.async.cg.shared.global [%0], [%1], 16;" :: "r"(saddr), "l"(gaddr));
}
#define CP_COMMIT() asm volatile("cp.async.commit_group;" ::: "memory")
#define CP_WAIT1()  asm volatile("cp.async.wait_group 1;" ::: "memory")
#define CP_WAIT0()  asm volatile("cp.async.wait_group 0;" ::: "memory")

// s8 IMMA m16n8k32, s32 accumulate (sm_80 ISA, valid on plain sm_100)
__device__ __forceinline__ void imma_s8(int* d, const uint32_t* a, const uint32_t* b) {
    asm volatile(
        "mma.sync.aligned.m16n8k32.row.col.s32.s8.s8.s32 "
        "{%0,%1,%2,%3},{%4,%5,%6,%7},{%8,%9},{%0,%1,%2,%3};"
        : "+r"(d[0]), "+r"(d[1]), "+r"(d[2]), "+r"(d[3])
        : "r"(a[0]), "r"(a[1]), "r"(a[2]), "r"(a[3]), "r"(b[0]), "r"(b[1]));
}
__device__ __forceinline__ void ldsm_x4(uint32_t* r, uint32_t addr) {
    asm volatile("ldmatrix.sync.aligned.m8n8.x4.shared.b16 {%0,%1,%2,%3}, [%4];"
        : "=r"(r[0]), "=r"(r[1]), "=r"(r[2]), "=r"(r[3]) : "r"(addr));
}

__device__ __forceinline__ float wrap_pi(float v) {
    const float PI_F = 3.14159265358979323846f;
    const float TWO_PI_F = 6.28318530717958647692f;
    float t = fmodf(v + PI_F, TWO_PI_F);
    if (t < 0.f) t += TWO_PI_F;
    if (t >= TWO_PI_F) t -= TWO_PI_F;
    return t - PI_F;
}

// quantize v (|v| <= 1 after scaling by 'sc'=64/range): h + l digits
__device__ __forceinline__ void quant2(float v, float sc, signed char& h, signed char& l) {
    float t = v * sc;
    float hf = rintf(t);
    float lf = rintf((t - hf) * 128.f);
    h = (signed char)(int)hf;
    l = (signed char)(int)lf;
}

// ---------------------------------------------------------------------------
// Prepasses
// ---------------------------------------------------------------------------
__global__ void zero_globals() { g_kmax_bits = 0u; g_cand_cnt = 0u; }

__global__ void kappa_max(const float* __restrict__ kappa) {
    size_t i = (size_t)blockIdx.x * blockDim.x + threadIdx.x;
    float4 v = reinterpret_cast<const float4*>(kappa)[i];
    float m = fmaxf(fmaxf(fabsf(v.x), fabsf(v.y)), fmaxf(fabsf(v.z), fabsf(v.w)));
#pragma unroll
    for (int off = 16; off > 0; off >>= 1)
        m = fmaxf(m, __shfl_xor_sync(0xFFFFFFFFu, m, off));
    if ((threadIdx.x & 31) == 0)
        atomicMax(&g_kmax_bits, __float_as_uint(m));  // positive floats: uint order == float order
}

__global__ void prep_kappa_q(const float* __restrict__ kappa) {
    const float sc = 64.f / __uint_as_float(g_kmax_bits);
    size_t i = (size_t)blockIdx.x * blockDim.x + threadIdx.x;
    float4 v = reinterpret_cast<const float4*>(kappa)[i];
    char4 h, l;
    quant2(v.x, sc, h.x, l.x);
    quant2(v.y, sc, h.y, l.y);
    quant2(v.z, sc, h.z, l.z);
    quant2(v.w, sc, h.w, l.w);
    reinterpret_cast<char4*>(g_kh)[i] = h;
    reinterpret_cast<char4*>(g_kl)[i] = l;
}

__global__ void prep_x_q(const float* __restrict__ x) {
    size_t i = (size_t)blockIdx.x * blockDim.x + threadIdx.x;
    float4 v = reinterpret_cast<const float4*>(x)[i];
    float s0, c0, s1, c1, s2, c2, s3, c3;
    sincosf(v.x, &s0, &c0);
    sincosf(v.y, &s1, &c1);
    sincosf(v.z, &s2, &c2);
    sincosf(v.w, &s3, &c3);
    char4 sh, sl, ch, cl;
    quant2(s0, 64.f, sh.x, sl.x);  quant2(c0, 64.f, ch.x, cl.x);
    quant2(s1, 64.f, sh.y, sl.y);  quant2(c1, 64.f, ch.y, cl.y);
    quant2(s2, 64.f, sh.z, sl.z);  quant2(c2, 64.f, ch.z, cl.z);
    quant2(s3, 64.f, sh.w, sl.w);  quant2(c3, 64.f, ch.w, cl.w);
    reinterpret_cast<char4*>(g_sh)[i] = sh;
    reinterpret_cast<char4*>(g_sl)[i] = sl;
    reinterpret_cast<char4*>(g_ch)[i] = ch;
    reinterpret_cast<char4*>(g_cl)[i] = cl;
}

// ---------------------------------------------------------------------------
// Main GEMM: int8 Ozaki 3-product, dual accumulators.
//   CTA 128(m) x 64(n), 256 threads, 8 warps (4m x 2n), warp tile 32x32.
//   BK=32 (one k32 IMMA step per stage). 48B-pitch int8 rows in smem.
// ---------------------------------------------------------------------------
#define BK 32
#define PITCH 48
#define OFF_CH 0
#define OFF_CL (128 * PITCH)          // 6144
#define OFF_SH (2 * 128 * PITCH)      // 12288
#define OFF_SL (3 * 128 * PITCH)      // 18432
#define OFF_KH (4 * 128 * PITCH)      // 24576
#define OFF_KL (4 * 128 * PITCH + 64 * PITCH)  // 27648
#define STAGE_B (4 * 128 * PITCH + 2 * 64 * PITCH)  // 30720
#define NBUF 3
#define SM_TOTAL (NBUF * STAGE_B)     // 92160
#define NSTAGES (DIM / BK)            // 128

__global__ __launch_bounds__(256, 1)
void resonator_imma_kernel(const float* __restrict__ x,
                           const float* __restrict__ omega,
                           float* __restrict__ out) {
    extern __shared__ __align__(128) char smem[];
    const uint32_t sbase = smem_u32(smem);

    const int tid  = threadIdx.x;
    const int wid  = tid >> 5;
    const int lane = tid & 31;
    const int g    = lane >> 2;
    const int tg   = lane & 3;

    // supertile swizzle: 32 m-tiles x 64 n-tiles, groups of 8 n-tiles
    const int bid = blockIdx.x;
    const int GROUP = 8;
    const int sg = bid / (32 * GROUP);
    const int r  = bid % (32 * GROUP);
    const int ty = r / GROUP;               // m tile 0..31
    const int tx = sg * GROUP + (r % GROUP);// n tile 0..63
    const int bm = ty * 128;
    const int bn = tx * 64;

    const int wm = (wid >> 1) * 32;   // 4 m-warps
    const int wn = (wid & 1) * 32;    // 2 n-warps

    // ---- loaders ----
    // A tensors: 128 rows x 2 halves -> thread t: row=t>>1, half=t&1 (1 chunk per tensor)
    // K tensors: 64 rows x 2 halves x 2 tensors -> thread t: tensor=t>>7, row=(t&127)>>1, half=t&1
    const int arow  = tid >> 1;
    const int ahalf = tid & 1;
    const int krow  = (tid & 127) >> 1;
    const int ktsel = tid >> 7;
    const size_t aoff_g = (size_t)(bm + arow) * DIM + ahalf * 16;
    const size_t koff_g = (size_t)(bn + krow) * DIM + ahalf * 16;
    const signed char* pCH = g_ch + aoff_g;
    const signed char* pCL = g_cl + aoff_g;
    const signed char* pSH = g_sh + aoff_g;
    const signed char* pSL = g_sl + aoff_g;
    const signed char* pKx = (ktsel ? g_kl : g_kh) + koff_g;
    const uint32_t sA = (uint32_t)(arow * PITCH + ahalf * 16);
    const uint32_t sK = (uint32_t)((ktsel ? OFF_KL : OFF_KH) + krow * PITCH + ahalf * 16);

    // ---- ldmatrix addresses (within-tile float offsets in bytes) ----
    // A x4: matrices (r0-7,k0),(r8-15,k0),(r0-7,k16),(r8-15,k16)
    //   thread: m=lane>>3: row=(m&1)*8+(lane&7), khalf=m>>1
    const int a_row_l = ((lane >> 3) & 1) * 8 + (lane & 7);
    const int a_kh_l  = (lane >> 4) & 1;
    // B x4 (pair p covers n-octets 2p,2p+1): m=lane>>3: nrow=(m>>1)*8+(lane&7), khalf=m&1
    const int b_row_l = ((lane >> 4) & 1) * 8 + (lane & 7);
    const int b_kh_l  = (lane >> 3) & 1;

    int kc_hh[2][4][4], kc_cr[2][4][4], ks_hh[2][4][4], ks_cr[2][4][4];
#pragma unroll
    for (int mt = 0; mt < 2; ++mt)
#pragma unroll
        for (int nt = 0; nt < 4; ++nt)
#pragma unroll
            for (int e = 0; e < 4; ++e) {
                kc_hh[mt][nt][e] = 0; kc_cr[mt][nt][e] = 0;
                ks_hh[mt][nt][e] = 0; ks_cr[mt][nt][e] = 0;
            }

    // prologue: stages 0,1
#pragma unroll
    for (int p = 0; p < 2; ++p) {
        const uint32_t sb = sbase + p * STAGE_B;
        const size_t ko = (size_t)p * BK;
        cp_async16(sb + OFF_CH + sA, pCH + ko);
        cp_async16(sb + OFF_CL + sA, pCL + ko);
        cp_async16(sb + OFF_SH + sA, pSH + ko);
        cp_async16(sb + OFF_SL + sA, pSL + ko);
        cp_async16(sb + sK, pKx + ko);
        CP_COMMIT();
    }

    for (int s = 0; s < NSTAGES; ++s) {
        if (s + 2 < NSTAGES) {
            const uint32_t sb = sbase + ((s + 2) % NBUF) * STAGE_B;
            const size_t ko = (size_t)(s + 2) * BK;
            cp_async16(sb + OFF_CH + sA, pCH + ko);
            cp_async16(sb + OFF_CL + sA, pCL + ko);
            cp_async16(sb + OFF_SH + sA, pSH + ko);
            cp_async16(sb + OFF_SL + sA, pSL + ko);
            cp_async16(sb + sK, pKx + ko);
            CP_COMMIT();
            CP_WAIT1();
        } else {
            CP_WAIT0();
        }
        __syncthreads();

        const uint32_t sb = sbase + (s % NBUF) * STAGE_B;

        // B fragments: kh, kl (n32 = 2 x4 each? n32 needs octets 0..3 -> pairs p=0,1)
        uint32_t bKH[4][2], bKL[4][2];
#pragma unroll
        for (int p = 0; p < 2; ++p) {
            uint32_t q[4];
            uint32_t addr = sb + OFF_KH +
                (uint32_t)((wn + p * 16 + b_row_l) * PITCH + b_kh_l * 16);
            ldsm_x4(q, addr);
            bKH[2 * p][0] = q[0]; bKH[2 * p][1] = q[1];
            bKH[2 * p + 1][0] = q[2]; bKH[2 * p + 1][1] = q[3];
            addr = sb + OFF_KL +
                (uint32_t)((wn + p * 16 + b_row_l) * PITCH + b_kh_l * 16);
            ldsm_x4(q, addr);
            bKL[2 * p][0] = q[0]; bKL[2 * p][1] = q[1];
            bKL[2 * p + 1][0] = q[2]; bKL[2 * p + 1][1] = q[3];
        }

        uint32_t aX[2][4];
        // ch: kc_hh += ch*kh ; kc_cr += ch*kl
#pragma unroll
        for (int mt = 0; mt < 2; ++mt)
            ldsm_x4(aX[mt], sb + OFF_CH +
                (uint32_t)((wm + mt * 16 + a_row_l) * PITCH + a_kh_l * 16));
#pragma unroll
        for (int mt = 0; mt < 2; ++mt)
#pragma unroll
            for (int nt = 0; nt < 4; ++nt) {
                imma_s8(kc_hh[mt][nt], aX[mt], bKH[nt]);
                imma_s8(kc_cr[mt][nt], aX[mt], bKL[nt]);
            }
        // cl: kc_cr += cl*kh
#pragma unroll
        for (int mt = 0; mt < 2; ++mt)
            ldsm_x4(aX[mt], sb + OFF_CL +
                (uint32_t)((wm + mt * 16 + a_row_l) * PITCH + a_kh_l * 16));
#pragma unroll
        for (int mt = 0; mt < 2; ++mt)
#pragma unroll
            for (int nt = 0; nt < 4; ++nt)
                imma_s8(kc_cr[mt][nt], aX[mt], bKH[nt]);
        // sh: ks_hh += sh*kh ; ks_cr += sh*kl
#pragma unroll
        for (int mt = 0; mt < 2; ++mt)
            ldsm_x4(aX[mt], sb + OFF_SH +
                (uint32_t)((wm + mt * 16 + a_row_l) * PITCH + a_kh_l * 16));
#pragma unroll
        for (int mt = 0; mt < 2; ++mt)
#pragma unroll
            for (int nt = 0; nt < 4; ++nt) {
                imma_s8(ks_hh[mt][nt], aX[mt], bKH[nt]);
                imma_s8(ks_cr[mt][nt], aX[mt], bKL[nt]);
            }
        // sl: ks_cr += sl*kh
#pragma unroll
        for (int mt = 0; mt < 2; ++mt)
            ldsm_x4(aX[mt], sb + OFF_SL +
                (uint32_t)((wm + mt * 16 + a_row_l) * PITCH + a_kh_l * 16));
#pragma unroll
        for (int mt = 0; mt < 2; ++mt)
#pragma unroll
            for (int nt = 0; nt < 4; ++nt)
                imma_s8(ks_cr[mt][nt], aX[mt], bKH[nt]);

        __syncthreads();
    }

    // -------------------- fused epilogue --------------------
    const float DT = 0.1f;
    const float mK = __uint_as_float(g_kmax_bits) / 64.f;   // kappa scale (per 2^-6 digit)
    const float S_HH = mK * (1.f / 64.f);                   // 2^-6 * 2^-6 * mK*64... see below
    // value = h*2^-6 + l*2^-13 (unit scale); kappa = mK64*(h*2^-6+l*2^-13), mK64 = kmax/64*64
    // kc = kmax_based: c*k sum = (kmax) * [ hh*2^-12 + cr*2^-19 ] with kmax absorbed:
    const float kmax = __uint_as_float(g_kmax_bits);
    const float SC_HH = kmax * (1.f / 4096.f);      // 2^-12
    const float SC_CR = kmax * (1.f / 524288.f);    // 2^-19
    (void)mK; (void)S_HH;

#pragma unroll
    for (int mt = 0; mt < 2; ++mt) {
#pragma unroll
        for (int half = 0; half < 2; ++half) {
            const int b = bm + wm + mt * 16 + g + half * 8;
            const size_t rowoff = (size_t)b * DIM;
#pragma unroll
            for (int nt = 0; nt < 4; ++nt) {
                const int i = bn + wn + nt * 8 + tg * 2;
                float2 xv = *reinterpret_cast<const float2*>(x + rowoff + i);
                float2 ov = __ldg(reinterpret_cast<const float2*>(omega + i));
                float2 o;
                {
                    const float kcv = (float)kc_hh[mt][nt][half * 2] * SC_HH
                                    + (float)kc_cr[mt][nt][half * 2] * SC_CR;
                    const float ksv = (float)ks_hh[mt][nt][half * 2] * SC_HH
                                    + (float)ks_cr[mt][nt][half * 2] * SC_CR;
                    float sv, cv;
                    sincosf(xv.x, &sv, &cv);
                    o.x = wrap_pi(xv.x + DT * (ov.x + sv * kcv - cv * ksv));
                }
                {
                    const float kcv = (float)kc_hh[mt][nt][half * 2 + 1] * SC_HH
                                    + (float)kc_cr[mt][nt][half * 2 + 1] * SC_CR;
                    const float ksv = (float)ks_hh[mt][nt][half * 2 + 1] * SC_HH
                                    + (float)ks_cr[mt][nt][half * 2 + 1] * SC_CR;
                    float sv, cv;
                    sincosf(xv.y, &sv, &cv);
                    o.y = wrap_pi(xv.y + DT * (ov.y + sv * kcv - cv * ksv));
                }
                *reinterpret_cast<float2*>(out + rowoff + i) = o;
            }
        }
    }
}

// ---------------------------------------------------------------------------
// Fixup (unchanged: exact fp32 recompute of boundary-adjacent outputs)
// ---------------------------------------------------------------------------
__global__ void scan_boundary(const float* __restrict__ out) {
    const float PI_F = 3.14159265358979323846f;
    const float THR = 4e-3f;
    size_t i = (size_t)blockIdx.x * blockDim.x + threadIdx.x;
    float4 v = reinterpret_cast<const float4*>(out)[i];
    const float a0 = fabsf(fabsf(v.x) - PI_F);
    const float a1 = fabsf(fabsf(v.y) - PI_F);
    const float a2 = fabsf(fabsf(v.z) - PI_F);
    const float a3 = fabsf(fabsf(v.w) - PI_F);
    if (a0 < THR || a1 < THR || a2 < THR || a3 < THR) {
        unsigned base = (unsigned)(i * 4);
        if (a0 < THR) { unsigned k = atomicAdd(&g_cand_cnt, 1u); if (k < CAND_CAP) g_cand[k] = base + 0; }
        if (a1 < THR) { unsigned k = atomicAdd(&g_cand_cnt, 1u); if (k < CAND_CAP) g_cand[k] = base + 1; }
        if (a2 < THR) { unsigned k = atomicAdd(&g_cand_cnt, 1u); if (k < CAND_CAP) g_cand[k] = base + 2; }
        if (a3 < THR) { unsigned k = atomicAdd(&g_cand_cnt, 1u); if (k < CAND_CAP) g_cand[k] = base + 3; }
    }
}

__global__ void fixup_apply(const float* __restrict__ x,
                            const float* __restrict__ kappa,
                            const float* __restrict__ omega,
                            float* __restrict__ out) {
    const int warps_total = (gridDim.x * blockDim.x) >> 5;
    const int warp_id = ((blockIdx.x * blockDim.x) + threadIdx.x) >> 5;
    const int lane = threadIdx.x & 31;
    unsigned cnt = g_cand_cnt;
    if (cnt > CAND_CAP) cnt = CAND_CAP;

    for (unsigned w = warp_id; w < cnt; w += warps_total) {
        const unsigned idx = g_cand[w];
        const int b = (int)(idx / DIM);
        const int i = (int)(idx % DIM);
        const float* xrow = x + (size_t)b * DIM;
        const float* krow = kappa + (size_t)i * DIM;
        float kcv = 0.f, ksv = 0.f;
        for (int j = lane; j < DIM; j += 32) {
            float sv, cv;
            sincosf(xrow[j], &sv, &cv);
            const float kv = krow[j];
            kcv = fmaf(kv, cv, kcv);
            ksv = fmaf(kv, sv, ksv);
        }
#pragma unroll
        for (int off = 16; off > 0; off >>= 1) {
            kcv += __shfl_down_sync(0xFFFFFFFFu, kcv, off);
            ksv += __shfl_down_sync(0xFFFFFFFFu, ksv, off);
        }
        if (lane == 0) {
            const float xi = xrow[i];
            float sv, cv;
            sincosf(xi, &sv, &cv);
            const float v = xi + 0.1f * (omega[i] + sv * kcv - cv * ksv);
            out[idx] = wrap_pi(v);
        }
    }
}

// ---------------------------------------------------------------------------
extern "C" void kernel_launch(void* const* d_in, const int* in_sizes, int n_in,
                              void* d_out, int out_size) {
    const float* x     = (const float*)d_in[0];
    const float* kappa = (const float*)d_in[1];
    const float* omega = (const float*)d_in[2];
    float* out = (float*)d_out;

    cudaFuncSetAttribute(resonator_imma_kernel,
                         cudaFuncAttributeMaxDynamicSharedMemorySize, SM_TOTAL);

    const int f4 = (int)(NTOT / 4);
    zero_globals<<<1, 1>>>();
    kappa_max<<<f4 / 256, 256>>>(kappa);
    prep_kappa_q<<<f4 / 256, 256>>>(kappa);
    prep_x_q<<<f4 / 256, 256>>>(x);
    resonator_imma_kernel<<<2048, 256, SM_TOTAL>>>(x, omega, out);
    scan_boundary<<<f4 / 256, 256>>>(out);
    fixup_apply<<<128, 256>>>(x, kappa, omega, out);
}